// round 4
// baseline (speedup 1.0000x reference)
#include <cuda_runtime.h>
#include <cuda_bf16.h>
#include <math.h>
#include <stdint.h>

#define B_     1024
#define VOCAB  32000
#define D_     128
#define KNEG   5
#define ROWS_T 7168          // 1024 vi + 1024 vo + 5120 neg
#define RTILES 56
#define SPLITS 10
#define CHUNK  3200          // VOCAB / SPLITS
#define ITERS  100           // CHUNK / 32

// ---------------- device scratch ----------------
__device__ float g_part[SPLITS][ROWS_T][D_];   // split-K partials (36.7 MB)
__device__ float g_s[B_];
__device__ float g_bm[B_ * KNEG];

// ---------------- helpers ----------------
__device__ __forceinline__ uint32_t pack_bf16(float lo, float hi) {
    uint32_t u;
    asm("cvt.rn.bf16x2.f32 %0, %1, %2;" : "=r"(u) : "f"(hi), "f"(lo));
    return u;
}

// m16n8k16 bf16 mma, row.col, fp32 accumulate
__device__ __forceinline__ void mma16(float c[4], const uint32_t a[4], const uint32_t b[2]) {
    asm volatile(
        "mma.sync.aligned.m16n8k16.row.col.f32.bf16.bf16.f32 "
        "{%0,%1,%2,%3}, {%4,%5,%6,%7}, {%8,%9}, {%0,%1,%2,%3};"
        : "+f"(c[0]), "+f"(c[1]), "+f"(c[2]), "+f"(c[3])
        : "r"(a[0]), "r"(a[1]), "r"(a[2]), "r"(a[3]), "r"(b[0]), "r"(b[1]));
}

// ---------------- kernel 1: C_part[sp] = X_tile @ Y_chunk  (bf16 HMMA, pipelined) ----------------
// grid (56 row-tiles, 10 splits).  CTA tile 128m x 128n, BK=32, 256 thr (8 warps 4m x 2n).
#define PITCH 20   // uint32 pitch: conflict-free fragment reads, 8B-aligned rows
__global__ __launch_bounds__(256, 2) void gemm_all(const float* __restrict__ vi,
                                                   const float* __restrict__ vo,
                                                   const float* __restrict__ neg,
                                                   const float* __restrict__ V,
                                                   const float* __restrict__ U) {
    __shared__ uint32_t As[2][128 * PITCH];   // [m][kpair] bf16x2
    __shared__ uint32_t Bs[2][128 * PITCH];   // [n][kpair] bf16x2

    const int mt = blockIdx.x;                // row-tile 0..55
    const int sp = blockIdx.y;                // split   0..9
    const int row0 = mt * 128;
    const float* X = (mt < 8)  ? vi  + (size_t)row0 * VOCAB
                   : (mt < 16) ? vo  + (size_t)(row0 - 1024) * VOCAB
                               : neg + (size_t)(row0 - 2048) * VOCAB;
    const float* Y = (mt < 8) ? V : U;
    const int kk0 = sp * CHUNK;

    const int tid = threadIdx.x, lane = tid & 31, wid = tid >> 5;
    const int g = lane >> 2, t = lane & 3;
    const int wm = wid >> 1, wn = wid & 1;

    // loader roles
    const int arow = tid >> 1;                 // 128 rows
    const int akp0 = (tid & 1) * 8;            // kpair base (2 threads per row)
    const int brow = tid >> 3;                 // 32 k-rows of Y
    const int bd0  = (tid & 7) * 4;            // d base, +s*32

    float c[2][8][4] = {};
    float4 xa[4], yb[4];

    // prefetch iter 0
    {
        const float* xr = X + (size_t)arow * VOCAB + kk0;
        #pragma unroll
        for (int s = 0; s < 4; s++) xa[s] = *(const float4*)(xr + akp0 * 2 + s * 4);
        const float* yr = Y + (size_t)(kk0 + brow) * D_;
        #pragma unroll
        for (int s = 0; s < 4; s++) yb[s] = *(const float4*)(yr + bd0 + s * 32);
    }

    int buf = 0;
    for (int it = 0; it < ITERS; it++) {
        // stage regs -> smem
        {
            uint32_t* ap = &As[buf][arow * PITCH + akp0];
            #pragma unroll
            for (int s = 0; s < 4; s++) {
                ap[s * 2]     = pack_bf16(xa[s].x, xa[s].y);
                ap[s * 2 + 1] = pack_bf16(xa[s].z, xa[s].w);
            }
            __nv_bfloat16* bp = (__nv_bfloat16*)&Bs[buf][0];
            #pragma unroll
            for (int s = 0; s < 4; s++) {
                int d = bd0 + s * 32;
                bp[(d + 0) * (2 * PITCH) + brow] = __float2bfloat16(yb[s].x);
                bp[(d + 1) * (2 * PITCH) + brow] = __float2bfloat16(yb[s].y);
                bp[(d + 2) * (2 * PITCH) + brow] = __float2bfloat16(yb[s].z);
                bp[(d + 3) * (2 * PITCH) + brow] = __float2bfloat16(yb[s].w);
            }
        }
        __syncthreads();

        // prefetch next iter while MMA runs
        if (it + 1 < ITERS) {
            const int kk = kk0 + (it + 1) * 32;
            const float* xr = X + (size_t)arow * VOCAB + kk;
            #pragma unroll
            for (int s = 0; s < 4; s++) xa[s] = *(const float4*)(xr + akp0 * 2 + s * 4);
            const float* yr = Y + (size_t)(kk + brow) * D_;
            #pragma unroll
            for (int s = 0; s < 4; s++) yb[s] = *(const float4*)(yr + bd0 + s * 32);
        }

        // MMA: 2 k16-steps
        #pragma unroll
        for (int ks = 0; ks < 2; ks++) {
            const int kb = ks * 8;
            uint32_t a[2][4];
            #pragma unroll
            for (int i = 0; i < 2; i++) {
                int m = wm * 32 + i * 16;
                a[i][0] = As[buf][(m + g) * PITCH + kb + t];
                a[i][1] = As[buf][(m + g + 8) * PITCH + kb + t];
                a[i][2] = As[buf][(m + g) * PITCH + kb + t + 4];
                a[i][3] = As[buf][(m + g + 8) * PITCH + kb + t + 4];
            }
            #pragma unroll
            for (int j = 0; j < 8; j++) {
                int n = wn * 64 + j * 8 + g;
                uint32_t b[2];
                b[0] = Bs[buf][n * PITCH + kb + t];
                b[1] = Bs[buf][n * PITCH + kb + t + 4];
                mma16(c[0][j], a[0], b);
                mma16(c[1][j], a[1], b);
            }
        }
        buf ^= 1;
        __syncthreads();
    }

    // epilogue: disjoint partial writes (no atomics)
    float* P = &g_part[sp][row0][0];
    #pragma unroll
    for (int i = 0; i < 2; i++) {
        #pragma unroll
        for (int j = 0; j < 8; j++) {
            int m = wm * 32 + i * 16;
            int col = wn * 64 + j * 8 + 2 * t;
            *(float2*)&P[(size_t)(m + g) * D_ + col]     = make_float2(c[i][j][0], c[i][j][1]);
            *(float2*)&P[(size_t)(m + g + 8) * D_ + col] = make_float2(c[i][j][2], c[i][j][3]);
        }
    }
}

// ---------------- kernel 2: reduce partials + per-b dot products ----------------
// one warp per batch row b: E = C[b], P = C[1024+b], N_k = C[2048 + b*5 + k]
__global__ __launch_bounds__(256) void finalize_a() {
    const int wid = threadIdx.x >> 5, lane = threadIdx.x & 31;
    const int b = blockIdx.x * 8 + wid;
    const int d = lane * 4;

    float4 e = make_float4(0.f, 0.f, 0.f, 0.f);
    float4 p = make_float4(0.f, 0.f, 0.f, 0.f);
    float4 nk[KNEG];
    #pragma unroll
    for (int k = 0; k < KNEG; k++) nk[k] = make_float4(0.f, 0.f, 0.f, 0.f);

    #pragma unroll
    for (int sp = 0; sp < SPLITS; sp++) {
        float4 v;
        v = *(const float4*)&g_part[sp][b][d];
        e.x += v.x; e.y += v.y; e.z += v.z; e.w += v.w;
        v = *(const float4*)&g_part[sp][1024 + b][d];
        p.x += v.x; p.y += v.y; p.z += v.z; p.w += v.w;
        #pragma unroll
        for (int k = 0; k < KNEG; k++) {
            v = *(const float4*)&g_part[sp][2048 + b * KNEG + k][d];
            nk[k].x += v.x; nk[k].y += v.y; nk[k].z += v.z; nk[k].w += v.w;
        }
    }

    float s = e.x * p.x + e.y * p.y + e.z * p.z + e.w * p.w;
    float bm[KNEG];
    #pragma unroll
    for (int k = 0; k < KNEG; k++)
        bm[k] = e.x * nk[k].x + e.y * nk[k].y + e.z * nk[k].z + e.w * nk[k].w;

    #pragma unroll
    for (int off = 16; off; off >>= 1) {
        s += __shfl_xor_sync(0xffffffffu, s, off);
        #pragma unroll
        for (int k = 0; k < KNEG; k++)
            bm[k] += __shfl_xor_sync(0xffffffffu, bm[k], off);
    }
    if (lane == 0) {
        g_s[b] = s;
        #pragma unroll
        for (int k = 0; k < KNEG; k++) g_bm[b * KNEG + k] = bm[k];
    }
}

// ---------------- kernel 3: loss ----------------
__device__ __forceinline__ float logsig(float x) {
    return fminf(x, 0.f) - log1pf(expf(-fabsf(x)));
}

__global__ void finalize_kernel(float* __restrict__ out) {
    __shared__ float red[B_];
    int b = threadIdx.x;
    float left  = logsig(g_s[b]);
    float right = 0.f;
    #pragma unroll
    for (int k = 0; k < KNEG; k++)
        right += logsig(-g_bm[b * KNEG + k]);
    red[b] = -(left + right);
    __syncthreads();
    for (int off = B_ / 2; off > 0; off >>= 1) {
        if (b < off) red[b] += red[b + off];
        __syncthreads();
    }
    if (b == 0) out[0] = red[0] / (float)B_;
}

// ---------------- launch ----------------
extern "C" void kernel_launch(void* const* d_in, const int* in_sizes, int n_in,
                              void* d_out, int out_size) {
    const float* vi  = (const float*)d_in[0];   // [B, VOC]
    const float* vo  = (const float*)d_in[1];   // [B, VOC]
    const float* neg = (const float*)d_in[2];   // [B, K, VOC]
    const float* V   = (const float*)d_in[3];   // [VOC, D]
    const float* U   = (const float*)d_in[4];   // [VOC, D]
    float* out = (float*)d_out;

    gemm_all<<<dim3(RTILES, SPLITS), 256>>>(vi, vo, neg, V, U);
    finalize_a<<<B_ / 8, 256>>>();
    finalize_kernel<<<1, B_>>>(out);
}

// round 5
// speedup vs baseline: 1.0148x; 1.0148x over previous
#include <cuda_runtime.h>
#include <cuda_bf16.h>
#include <math.h>
#include <stdint.h>

#define B_     1024
#define VOCAB  32000
#define D_     128
#define KNEG   5
#define ROWS_T 7168          // 1024 vi + 1024 vo + 5120 neg
#define RTILES 56
#define SPLITS 10
#define CHUNK  3200          // VOCAB / SPLITS
#define ITERS  100           // CHUNK / 32

// smem layout (bytes):  A: [m=128][k=32] bf16, row pitch 80B.  B: [k=32][d=128] bf16,
// row 256B, 16B-chunk XOR-swizzled by (k&7).  Double buffered.
#define A_ROWB  80
#define A_BUF   (128 * A_ROWB)    // 10240
#define B_BUF   (32 * 256)        // 8192
#define SMEMSZ  (2 * A_BUF + 2 * B_BUF)

// ---------------- device scratch ----------------
__device__ float g_part[SPLITS][ROWS_T][D_];   // split-K partials
__device__ float g_s[B_];
__device__ float g_bm[B_ * KNEG];

// ---------------- helpers ----------------
__device__ __forceinline__ uint32_t smem_u32(const void* p) {
    uint32_t a;
    asm("{ .reg .u64 t; cvta.to.shared.u64 t, %1; cvt.u32.u64 %0, t; }" : "=r"(a) : "l"(p));
    return a;
}
__device__ __forceinline__ uint32_t pack_bf16(float lo, float hi) {
    uint32_t u;
    asm("cvt.rn.bf16x2.f32 %0, %1, %2;" : "=r"(u) : "f"(hi), "f"(lo));
    return u;
}
__device__ __forceinline__ void ldsm4(uint32_t r[4], uint32_t addr) {
    asm volatile("ldmatrix.sync.aligned.m8n8.x4.shared.b16 {%0,%1,%2,%3}, [%4];"
                 : "=r"(r[0]), "=r"(r[1]), "=r"(r[2]), "=r"(r[3]) : "r"(addr));
}
__device__ __forceinline__ void ldsm4t(uint32_t r[4], uint32_t addr) {
    asm volatile("ldmatrix.sync.aligned.m8n8.x4.trans.shared.b16 {%0,%1,%2,%3}, [%4];"
                 : "=r"(r[0]), "=r"(r[1]), "=r"(r[2]), "=r"(r[3]) : "r"(addr));
}
__device__ __forceinline__ void mma16(float c[4], const uint32_t a[4], const uint32_t b[2]) {
    asm volatile(
        "mma.sync.aligned.m16n8k16.row.col.f32.bf16.bf16.f32 "
        "{%0,%1,%2,%3}, {%4,%5,%6,%7}, {%8,%9}, {%0,%1,%2,%3};"
        : "+f"(c[0]), "+f"(c[1]), "+f"(c[2]), "+f"(c[3])
        : "r"(a[0]), "r"(a[1]), "r"(a[2]), "r"(a[3]), "r"(b[0]), "r"(b[1]));
}

// ---------------- kernel 1: C_part[sp] = X_tile @ Y_chunk ----------------
__global__ __launch_bounds__(256, 2) void gemm_all(const float* __restrict__ vi,
                                                   const float* __restrict__ vo,
                                                   const float* __restrict__ neg,
                                                   const float* __restrict__ V,
                                                   const float* __restrict__ U) {
    __shared__ __align__(16) char smem[SMEMSZ];

    const int mt = blockIdx.x;                // row-tile 0..55
    const int sp = blockIdx.y;                // split   0..9
    const int row0 = mt * 128;
    const float* X = (mt < 8)  ? vi  + (size_t)row0 * VOCAB
                   : (mt < 16) ? vo  + (size_t)(row0 - 1024) * VOCAB
                               : neg + (size_t)(row0 - 2048) * VOCAB;
    const float* Y = (mt < 8) ? V : U;
    const int kk0 = sp * CHUNK;

    const int tid = threadIdx.x, lane = tid & 31, wid = tid >> 5;
    const int wm = wid >> 1, wn = wid & 1;

    const uint32_t sb  = smem_u32(smem);
    const uint32_t sA0 = sb;                       // A buf0
    const uint32_t sB0 = sb + 2 * A_BUF;           // B buf0

    // ---- loader roles ----
    const int arow = tid >> 1;                     // 0..127 (m)
    const int akp0 = (tid & 1) * 8;                // uint32 kpair base (k offset = akp0*2)
    const int brow = tid >> 3;                     // 0..31  (k)
    const int dbase = (tid & 7) * 16;              // d base (16 d per thread)

    // ---- fragment load addresses (per-thread invariants, byte offsets) ----
    // A (non-trans): rows m, 80B pitch;  +i*16*80 per m-subtile, +ks*32 per k16-step
    const uint32_t a_off = (uint32_t)(wm * 32 + (lane & 15)) * A_ROWB + ((lane >> 4) << 4);
    // B (trans): row k = ks*16 + kl, 256B pitch; chunk = (nch ^ (lane&7)) * 16
    const int kl = (lane & 7) + ((lane >> 3) & 1) * 8;
    uint32_t b_swz[4];
    #pragma unroll
    for (int jj = 0; jj < 4; jj++)
        b_swz[jj] = (uint32_t)(((wn * 8 + jj * 2 + (lane >> 4)) ^ (lane & 7)) << 4);
    const uint32_t b_off = (uint32_t)kl * 256;

    float c[2][8][4] = {};
    float4 xa[4], yb[4];

    // prefetch iter 0
    {
        const float* xr = X + (size_t)arow * VOCAB + kk0 + akp0 * 2;
        #pragma unroll
        for (int s = 0; s < 4; s++) xa[s] = *(const float4*)(xr + s * 4);
        const float* yr = Y + (size_t)(kk0 + brow) * D_ + dbase;
        #pragma unroll
        for (int s = 0; s < 4; s++) yb[s] = *(const float4*)(yr + s * 4);
    }

    uint32_t abuf = sA0, bbuf = sB0;
    for (int it = 0; it < ITERS; it++) {
        // ---- stage regs -> smem ----
        {
            uint32_t* ap = (uint32_t*)(size_t)0;  // use typed smem path
            ap = (uint32_t*)(smem + (abuf - sb)) + arow * (A_ROWB / 4) + akp0;
            #pragma unroll
            for (int s = 0; s < 4; s++) {
                ap[s * 2]     = pack_bf16(xa[s].x, xa[s].y);
                ap[s * 2 + 1] = pack_bf16(xa[s].z, xa[s].w);
            }
            uint32_t* bp = (uint32_t*)(smem + (bbuf - sb)) + brow * 64;
            #pragma unroll
            for (int s = 0; s < 4; s++) {
                int ch  = (dbase >> 3) + (s >> 1);
                int chs = ch ^ (brow & 7);
                uint32_t* q = bp + chs * 4 + (s & 1) * 2;
                q[0] = pack_bf16(yb[s].x, yb[s].y);
                q[1] = pack_bf16(yb[s].z, yb[s].w);
            }
        }
        __syncthreads();

        // ---- prefetch next ----
        if (it + 1 < ITERS) {
            const int kk = kk0 + (it + 1) * 32;
            const float* xr = X + (size_t)arow * VOCAB + kk + akp0 * 2;
            #pragma unroll
            for (int s = 0; s < 4; s++) xa[s] = *(const float4*)(xr + s * 4);
            const float* yr = Y + (size_t)(kk + brow) * D_ + dbase;
            #pragma unroll
            for (int s = 0; s < 4; s++) yb[s] = *(const float4*)(yr + s * 4);
        }

        // ---- MMA: 2 k16-steps, ldmatrix fragments ----
        #pragma unroll
        for (int ks = 0; ks < 2; ks++) {
            uint32_t af[2][4];
            ldsm4(af[0], abuf + a_off + ks * 32);
            ldsm4(af[1], abuf + a_off + 16 * A_ROWB + ks * 32);
            const uint32_t brow_b = bbuf + b_off + ks * 16 * 256;
            #pragma unroll
            for (int jj = 0; jj < 4; jj++) {
                uint32_t bf[4];
                ldsm4t(bf, brow_b + b_swz[jj]);
                mma16(c[0][jj * 2],     af[0], bf);
                mma16(c[0][jj * 2 + 1], af[0], bf + 2);
                mma16(c[1][jj * 2],     af[1], bf);
                mma16(c[1][jj * 2 + 1], af[1], bf + 2);
            }
        }
        abuf ^= A_BUF; bbuf ^= B_BUF;
        __syncthreads();
    }

    // ---- epilogue: disjoint partial writes ----
    const int g = lane >> 2, t = lane & 3;
    float* P = &g_part[sp][row0][0];
    #pragma unroll
    for (int i = 0; i < 2; i++) {
        #pragma unroll
        for (int j = 0; j < 8; j++) {
            int m = wm * 32 + i * 16;
            int col = wn * 64 + j * 8 + 2 * t;
            *(float2*)&P[(size_t)(m + g) * D_ + col]     = make_float2(c[i][j][0], c[i][j][1]);
            *(float2*)&P[(size_t)(m + g + 8) * D_ + col] = make_float2(c[i][j][2], c[i][j][3]);
        }
    }
}

// ---------------- kernel 2: reduce partials + per-b dot products ----------------
__global__ __launch_bounds__(256) void finalize_a() {
    const int wid = threadIdx.x >> 5, lane = threadIdx.x & 31;
    const int b = blockIdx.x * 8 + wid;
    const int d = lane * 4;

    float4 e = make_float4(0.f, 0.f, 0.f, 0.f);
    float4 p = make_float4(0.f, 0.f, 0.f, 0.f);
    float4 nk[KNEG];
    #pragma unroll
    for (int k = 0; k < KNEG; k++) nk[k] = make_float4(0.f, 0.f, 0.f, 0.f);

    #pragma unroll
    for (int sp = 0; sp < SPLITS; sp++) {
        float4 v;
        v = *(const float4*)&g_part[sp][b][d];
        e.x += v.x; e.y += v.y; e.z += v.z; e.w += v.w;
        v = *(const float4*)&g_part[sp][1024 + b][d];
        p.x += v.x; p.y += v.y; p.z += v.z; p.w += v.w;
        #pragma unroll
        for (int k = 0; k < KNEG; k++) {
            v = *(const float4*)&g_part[sp][2048 + b * KNEG + k][d];
            nk[k].x += v.x; nk[k].y += v.y; nk[k].z += v.z; nk[k].w += v.w;
        }
    }

    float s = e.x * p.x + e.y * p.y + e.z * p.z + e.w * p.w;
    float bm[KNEG];
    #pragma unroll
    for (int k = 0; k < KNEG; k++)
        bm[k] = e.x * nk[k].x + e.y * nk[k].y + e.z * nk[k].z + e.w * nk[k].w;

    #pragma unroll
    for (int off = 16; off; off >>= 1) {
        s += __shfl_xor_sync(0xffffffffu, s, off);
        #pragma unroll
        for (int k = 0; k < KNEG; k++)
            bm[k] += __shfl_xor_sync(0xffffffffu, bm[k], off);
    }
    if (lane == 0) {
        g_s[b] = s;
        #pragma unroll
        for (int k = 0; k < KNEG; k++) g_bm[b * KNEG + k] = bm[k];
    }
}

// ---------------- kernel 3: loss ----------------
__device__ __forceinline__ float logsig(float x) {
    return fminf(x, 0.f) - log1pf(expf(-fabsf(x)));
}

__global__ void finalize_kernel(float* __restrict__ out) {
    __shared__ float red[B_];
    int b = threadIdx.x;
    float left  = logsig(g_s[b]);
    float right = 0.f;
    #pragma unroll
    for (int k = 0; k < KNEG; k++)
        right += logsig(-g_bm[b * KNEG + k]);
    red[b] = -(left + right);
    __syncthreads();
    for (int off = B_ / 2; off > 0; off >>= 1) {
        if (b < off) red[b] += red[b + off];
        __syncthreads();
    }
    if (b == 0) out[0] = red[0] / (float)B_;
}

// ---------------- launch ----------------
extern "C" void kernel_launch(void* const* d_in, const int* in_sizes, int n_in,
                              void* d_out, int out_size) {
    const float* vi  = (const float*)d_in[0];   // [B, VOC]
    const float* vo  = (const float*)d_in[1];   // [B, VOC]
    const float* neg = (const float*)d_in[2];   // [B, K, VOC]
    const float* V   = (const float*)d_in[3];   // [VOC, D]
    const float* U   = (const float*)d_in[4];   // [VOC, D]
    float* out = (float*)d_out;

    gemm_all<<<dim3(RTILES, SPLITS), 256>>>(vi, vo, neg, V, U);
    finalize_a<<<B_ / 8, 256>>>();
    finalize_kernel<<<1, B_>>>(out);
}

// round 7
// speedup vs baseline: 1.1042x; 1.0881x over previous
#include <cuda_runtime.h>
#include <cuda_bf16.h>
#include <math.h>
#include <stdint.h>

#define B_     1024
#define VOCAB  32000
#define D_     128
#define KNEG   5
#define ROWS_T 7168          // 1024 vi + 1024 vo + 5120 neg
#define RTILES 28            // 256-row tiles
#define SPLITS 5
#define CHUNK  6400          // VOCAB / SPLITS
#define ITERS  200           // CHUNK / 32

// smem:  A: [m=256][k=32] bf16, row pitch 80B.  B: [k=32][d=128] bf16,
// row 256B, 16B-chunk XOR-swizzled by (k&7).  Double buffered (additive toggle).
#define A_ROWB  80
#define A_BUF   (256 * A_ROWB)    // 20480
#define B_BUF   (32 * 256)        // 8192
#define SMEMSZ  (2 * A_BUF + 2 * B_BUF)   // 57344

// ---------------- device scratch ----------------
__device__ float g_part[SPLITS][ROWS_T][D_];   // split-K partials (18.3 MB)
__device__ float g_s[B_];
__device__ float g_bm[B_ * KNEG];

// ---------------- helpers ----------------
__device__ __forceinline__ uint32_t smem_u32(const void* p) {
    uint32_t a;
    asm("{ .reg .u64 t; cvta.to.shared.u64 t, %1; cvt.u32.u64 %0, t; }" : "=r"(a) : "l"(p));
    return a;
}
__device__ __forceinline__ uint32_t pack_bf16(float lo, float hi) {
    uint32_t u;
    asm("cvt.rn.bf16x2.f32 %0, %1, %2;" : "=r"(u) : "f"(hi), "f"(lo));
    return u;
}
__device__ __forceinline__ void ldsm4(uint32_t r[4], uint32_t addr) {
    asm volatile("ldmatrix.sync.aligned.m8n8.x4.shared.b16 {%0,%1,%2,%3}, [%4];"
                 : "=r"(r[0]), "=r"(r[1]), "=r"(r[2]), "=r"(r[3]) : "r"(addr));
}
__device__ __forceinline__ void ldsm4t(uint32_t r[4], uint32_t addr) {
    asm volatile("ldmatrix.sync.aligned.m8n8.x4.trans.shared.b16 {%0,%1,%2,%3}, [%4];"
                 : "=r"(r[0]), "=r"(r[1]), "=r"(r[2]), "=r"(r[3]) : "r"(addr));
}
__device__ __forceinline__ void mma16(float c[4], const uint32_t a[4], const uint32_t b[2]) {
    asm volatile(
        "mma.sync.aligned.m16n8k16.row.col.f32.bf16.bf16.f32 "
        "{%0,%1,%2,%3}, {%4,%5,%6,%7}, {%8,%9}, {%0,%1,%2,%3};"
        : "+f"(c[0]), "+f"(c[1]), "+f"(c[2]), "+f"(c[3])
        : "r"(a[0]), "r"(a[1]), "r"(a[2]), "r"(a[3]), "r"(b[0]), "r"(b[1]));
}

// ---------------- kernel 1: C_part[sp] = X_tile @ Y_chunk ----------------
// CTA tile 256m x 128n, BK=32.  8 warps as 4(m) x 2(n), warp tile 64x64.
__global__ __launch_bounds__(256, 1) void gemm_all(const float* __restrict__ vi,
                                                   const float* __restrict__ vo,
                                                   const float* __restrict__ neg,
                                                   const float* __restrict__ V,
                                                   const float* __restrict__ U) {
    __shared__ __align__(16) char smem[SMEMSZ];

    const int mt = blockIdx.x;                // row-tile 0..27
    const int sp = blockIdx.y;                // split   0..4
    const int row0 = mt * 256;
    const float* X = (mt < 4) ? vi  + (size_t)row0 * VOCAB
                   : (mt < 8) ? vo  + (size_t)(row0 - 1024) * VOCAB
                              : neg + (size_t)(row0 - 2048) * VOCAB;
    const float* Y = (mt < 4) ? V : U;
    const int kk0 = sp * CHUNK;

    const int tid = threadIdx.x, lane = tid & 31, wid = tid >> 5;
    const int wm = wid >> 1, wn = wid & 1;    // 4 x 2

    const uint32_t sb  = smem_u32(smem);
    const uint32_t sA0 = sb;
    const uint32_t sB0 = sb + 2 * A_BUF;

    // ---- loader roles ----
    const int arow = tid;                     // one thread per m-row (full 64B of k)
    const int brow = tid >> 3;                // 8 threads per k-row
    const int dbase = (tid & 7) * 16;

    // ---- fragment addresses ----
    const uint32_t a_off = (uint32_t)(wm * 64 + (lane & 15)) * A_ROWB + ((lane >> 4) << 4);
    const int kl = (lane & 7) + ((lane >> 3) & 1) * 8;
    uint32_t b_swz[4];
    #pragma unroll
    for (int jj = 0; jj < 4; jj++)
        b_swz[jj] = (uint32_t)(((wn * 8 + jj * 2 + (lane >> 4)) ^ (lane & 7)) << 4);
    const uint32_t b_off = (uint32_t)kl * 256;

    float c[4][8][4] = {};
    float4 xa[8], yb[4];

    // prefetch iter 0
    {
        const float* xr = X + (size_t)arow * VOCAB + kk0;
        #pragma unroll
        for (int s = 0; s < 8; s++) xa[s] = *(const float4*)(xr + s * 4);
        const float* yr = Y + (size_t)(kk0 + brow) * D_ + dbase;
        #pragma unroll
        for (int s = 0; s < 4; s++) yb[s] = *(const float4*)(yr + s * 4);
    }

    for (int it = 0; it < ITERS; it++) {
        // additive double-buffer toggle (NO xor — base bits not guaranteed clear)
        const uint32_t aoff_buf = (it & 1) ? A_BUF : 0;
        const uint32_t boff_buf = (it & 1) ? B_BUF : 0;
        const uint32_t abuf = sA0 + aoff_buf;
        const uint32_t bbuf = sB0 + boff_buf;

        // ---- stage regs -> smem ----
        {
            uint4* ap = (uint4*)(smem + aoff_buf + arow * A_ROWB);
            #pragma unroll
            for (int s = 0; s < 4; s++) {
                ap[s] = make_uint4(pack_bf16(xa[2*s].x,   xa[2*s].y),
                                   pack_bf16(xa[2*s].z,   xa[2*s].w),
                                   pack_bf16(xa[2*s+1].x, xa[2*s+1].y),
                                   pack_bf16(xa[2*s+1].z, xa[2*s+1].w));
            }
            uint32_t* bp = (uint32_t*)(smem + 2 * A_BUF + boff_buf) + brow * 64;
            #pragma unroll
            for (int s = 0; s < 4; s++) {
                int ch  = (dbase >> 3) + (s >> 1);
                int chs = ch ^ (brow & 7);
                uint32_t* q = bp + chs * 4 + (s & 1) * 2;
                q[0] = pack_bf16(yb[s].x, yb[s].y);
                q[1] = pack_bf16(yb[s].z, yb[s].w);
            }
        }
        __syncthreads();

        // ---- prefetch next iter (overlaps with MMA below) ----
        if (it + 1 < ITERS) {
            const int kk = kk0 + (it + 1) * 32;
            const float* xr = X + (size_t)arow * VOCAB + kk;
            #pragma unroll
            for (int s = 0; s < 8; s++) xa[s] = *(const float4*)(xr + s * 4);
            const float* yr = Y + (size_t)(kk + brow) * D_ + dbase;
            #pragma unroll
            for (int s = 0; s < 4; s++) yb[s] = *(const float4*)(yr + s * 4);
        }

        // ---- MMA: 2 k16-steps ----
        #pragma unroll
        for (int ks = 0; ks < 2; ks++) {
            uint32_t af[4][4];
            #pragma unroll
            for (int i = 0; i < 4; i++)
                ldsm4(af[i], abuf + a_off + i * (16 * A_ROWB) + ks * 32);
            const uint32_t brow_b = bbuf + b_off + ks * 16 * 256;
            #pragma unroll
            for (int jj = 0; jj < 4; jj++) {
                uint32_t bf[4];
                ldsm4t(bf, brow_b + b_swz[jj]);
                #pragma unroll
                for (int i = 0; i < 4; i++) {
                    mma16(c[i][jj * 2],     af[i], bf);
                    mma16(c[i][jj * 2 + 1], af[i], bf + 2);
                }
            }
        }
        __syncthreads();
    }

    // ---- epilogue: disjoint partial writes ----
    const int g = lane >> 2, t = lane & 3;
    float* P = &g_part[sp][row0][0];
    #pragma unroll
    for (int i = 0; i < 4; i++) {
        #pragma unroll
        for (int j = 0; j < 8; j++) {
            int m = wm * 64 + i * 16;
            int col = wn * 64 + j * 8 + 2 * t;
            *(float2*)&P[(size_t)(m + g) * D_ + col]     = make_float2(c[i][j][0], c[i][j][1]);
            *(float2*)&P[(size_t)(m + g + 8) * D_ + col] = make_float2(c[i][j][2], c[i][j][3]);
        }
    }
}

// ---------------- kernel 2: reduce partials + per-b dot products ----------------
__global__ __launch_bounds__(256) void finalize_a() {
    const int wid = threadIdx.x >> 5, lane = threadIdx.x & 31;
    const int b = blockIdx.x * 8 + wid;
    const int d = lane * 4;

    float4 e = make_float4(0.f, 0.f, 0.f, 0.f);
    float4 p = make_float4(0.f, 0.f, 0.f, 0.f);
    float4 nk[KNEG];
    #pragma unroll
    for (int k = 0; k < KNEG; k++) nk[k] = make_float4(0.f, 0.f, 0.f, 0.f);

    #pragma unroll
    for (int sp = 0; sp < SPLITS; sp++) {
        float4 v;
        v = *(const float4*)&g_part[sp][b][d];
        e.x += v.x; e.y += v.y; e.z += v.z; e.w += v.w;
        v = *(const float4*)&g_part[sp][1024 + b][d];
        p.x += v.x; p.y += v.y; p.z += v.z; p.w += v.w;
        #pragma unroll
        for (int k = 0; k < KNEG; k++) {
            v = *(const float4*)&g_part[sp][2048 + b * KNEG + k][d];
            nk[k].x += v.x; nk[k].y += v.y; nk[k].z += v.z; nk[k].w += v.w;
        }
    }

    float s = e.x * p.x + e.y * p.y + e.z * p.z + e.w * p.w;
    float bm[KNEG];
    #pragma unroll
    for (int k = 0; k < KNEG; k++)
        bm[k] = e.x * nk[k].x + e.y * nk[k].y + e.z * nk[k].z + e.w * nk[k].w;

    #pragma unroll
    for (int off = 16; off; off >>= 1) {
        s += __shfl_xor_sync(0xffffffffu, s, off);
        #pragma unroll
        for (int k = 0; k < KNEG; k++)
            bm[k] += __shfl_xor_sync(0xffffffffu, bm[k], off);
    }
    if (lane == 0) {
        g_s[b] = s;
        #pragma unroll
        for (int k = 0; k < KNEG; k++) g_bm[b * KNEG + k] = bm[k];
    }
}

// ---------------- kernel 3: loss ----------------
__device__ __forceinline__ float logsig(float x) {
    return fminf(x, 0.f) - log1pf(expf(-fabsf(x)));
}

__global__ void finalize_kernel(float* __restrict__ out) {
    __shared__ float red[B_];
    int b = threadIdx.x;
    float left  = logsig(g_s[b]);
    float right = 0.f;
    #pragma unroll
    for (int k = 0; k < KNEG; k++)
        right += logsig(-g_bm[b * KNEG + k]);
    red[b] = -(left + right);
    __syncthreads();
    for (int off = B_ / 2; off > 0; off >>= 1) {
        if (b < off) red[b] += red[b + off];
        __syncthreads();
    }
    if (b == 0) out[0] = red[0] / (float)B_;
}

// ---------------- launch ----------------
extern "C" void kernel_launch(void* const* d_in, const int* in_sizes, int n_in,
                              void* d_out, int out_size) {
    const float* vi  = (const float*)d_in[0];   // [B, VOC]
    const float* vo  = (const float*)d_in[1];   // [B, VOC]
    const float* neg = (const float*)d_in[2];   // [B, K, VOC]
    const float* V   = (const float*)d_in[3];   // [VOC, D]
    const float* U   = (const float*)d_in[4];   // [VOC, D]
    float* out = (float*)d_out;

    gemm_all<<<dim3(RTILES, SPLITS), 256>>>(vi, vo, neg, V, U);
    finalize_a<<<B_ / 8, 256>>>();
    finalize_kernel<<<1, B_>>>(out);
}

// round 8
// speedup vs baseline: 1.7720x; 1.6048x over previous
#include <cuda_runtime.h>
#include <cuda_bf16.h>
#include <math.h>
#include <stdint.h>

#define B_     1024
#define VOCAB  32000
#define D_     128
#define KNEG   5
#define ROWS_T 7168          // 1024 vi + 1024 vo + 5120 neg
#define RTILES 28            // 256-row tiles
#define SPLITS 5
#define CHUNK  6400          // VOCAB / SPLITS
#define ITERS  200           // CHUNK / 32

// smem:  A: [m=256][k=32] bf16, row pitch 80B (64B data + 16B pad).
//        B: [k=32][d=128] bf16, row 256B, 16B-chunk XOR-swizzled by (k&7).
// Double buffered (additive toggle).
#define A_ROWB  80
#define A_BUF   (256 * A_ROWB)    // 20480
#define B_BUF   (32 * 256)        // 8192
#define SMEMSZ  (2 * A_BUF + 2 * B_BUF)   // 57344

// ---------------- device scratch ----------------
__device__ float g_part[SPLITS][ROWS_T][D_];   // split-K partials (18.3 MB)
__device__ float g_s[B_];
__device__ float g_bm[B_ * KNEG];

// ---------------- helpers ----------------
__device__ __forceinline__ uint32_t smem_u32(const void* p) {
    uint32_t a;
    asm("{ .reg .u64 t; cvta.to.shared.u64 t, %1; cvt.u32.u64 %0, t; }" : "=r"(a) : "l"(p));
    return a;
}
__device__ __forceinline__ uint32_t pack_bf16(float lo, float hi) {
    uint32_t u;
    asm("cvt.rn.bf16x2.f32 %0, %1, %2;" : "=r"(u) : "f"(hi), "f"(lo));
    return u;
}
__device__ __forceinline__ void ldsm4(uint32_t r[4], uint32_t addr) {
    asm volatile("ldmatrix.sync.aligned.m8n8.x4.shared.b16 {%0,%1,%2,%3}, [%4];"
                 : "=r"(r[0]), "=r"(r[1]), "=r"(r[2]), "=r"(r[3]) : "r"(addr));
}
__device__ __forceinline__ void ldsm4t(uint32_t r[4], uint32_t addr) {
    asm volatile("ldmatrix.sync.aligned.m8n8.x4.trans.shared.b16 {%0,%1,%2,%3}, [%4];"
                 : "=r"(r[0]), "=r"(r[1]), "=r"(r[2]), "=r"(r[3]) : "r"(addr));
}
__device__ __forceinline__ void mma16(float c[4], const uint32_t a[4], const uint32_t b[2]) {
    asm volatile(
        "mma.sync.aligned.m16n8k16.row.col.f32.bf16.bf16.f32 "
        "{%0,%1,%2,%3}, {%4,%5,%6,%7}, {%8,%9}, {%0,%1,%2,%3};"
        : "+f"(c[0]), "+f"(c[1]), "+f"(c[2]), "+f"(c[3])
        : "r"(a[0]), "r"(a[1]), "r"(a[2]), "r"(a[3]), "r"(b[0]), "r"(b[1]));
}

// ---------------- kernel 1: C_part[sp] = X_tile @ Y_chunk ----------------
// CTA tile 256m x 128n, BK=32.  8 warps as 4(m) x 2(n), warp tile 64x64.
__global__ __launch_bounds__(256, 1) void gemm_all(const float* __restrict__ vi,
                                                   const float* __restrict__ vo,
                                                   const float* __restrict__ neg,
                                                   const float* __restrict__ V,
                                                   const float* __restrict__ U) {
    __shared__ __align__(16) char smem[SMEMSZ];

    const int mt = blockIdx.x;                // row-tile 0..27
    const int sp = blockIdx.y;                // split   0..4
    const int row0 = mt * 256;
    const float* X = (mt < 4) ? vi  + (size_t)row0 * VOCAB
                   : (mt < 8) ? vo  + (size_t)(row0 - 1024) * VOCAB
                              : neg + (size_t)(row0 - 2048) * VOCAB;
    const float* Y = (mt < 4) ? V : U;
    const int kk0 = sp * CHUNK;

    const int tid = threadIdx.x, lane = tid & 31, wid = tid >> 5;
    const int wm = wid >> 1, wn = wid & 1;    // 4 x 2

    const uint32_t sb = smem_u32(smem);

    // ---- loader roles (COALESCED: consecutive lanes -> consecutive float4) ----
    // A: pass s (0..7): row = s*32 + (tid>>3), float4 col = tid&7  (warp = 4 rows)
    const int ar = tid >> 3;
    const int ac = tid & 7;
    // B: pass s (0..3): row = s*8 + (tid>>5), float4 col = lane    (warp = 1 row)
    const int br = tid >> 5;
    const int bc = lane;

    // ---- fragment addresses (unchanged from validated R5/R7 maps) ----
    const uint32_t a_off = (uint32_t)(wm * 64 + (lane & 15)) * A_ROWB + ((lane >> 4) << 4);
    const int kl = (lane & 7) + ((lane >> 3) & 1) * 8;
    uint32_t b_swz[4];
    #pragma unroll
    for (int jj = 0; jj < 4; jj++)
        b_swz[jj] = (uint32_t)(((wn * 8 + jj * 2 + (lane >> 4)) ^ (lane & 7)) << 4);
    const uint32_t b_off = (uint32_t)kl * 256;

    float c[4][8][4] = {};
    float4 xa[8], yb[4];

    // prefetch iter 0
    {
        #pragma unroll
        for (int s = 0; s < 8; s++)
            xa[s] = *(const float4*)(X + (size_t)(s * 32 + ar) * VOCAB + kk0 + ac * 4);
        #pragma unroll
        for (int s = 0; s < 4; s++)
            yb[s] = *(const float4*)(Y + (size_t)(kk0 + s * 8 + br) * D_ + bc * 4);
    }

    for (int it = 0; it < ITERS; it++) {
        const uint32_t aoff_buf = (it & 1) ? A_BUF : 0;
        const uint32_t boff_buf = (it & 1) ? B_BUF : 0;
        const uint32_t abuf = sb + aoff_buf;
        const uint32_t bbuf = sb + 2 * A_BUF + boff_buf;

        // ---- stage regs -> smem (bf16) ----
        {
            // A: 8B per pass at As[row][ac*8], pitch 80
            char* abase = smem + aoff_buf;
            #pragma unroll
            for (int s = 0; s < 8; s++) {
                uint2 v = make_uint2(pack_bf16(xa[s].x, xa[s].y),
                                     pack_bf16(xa[s].z, xa[s].w));
                *(uint2*)(abase + (s * 32 + ar) * A_ROWB + ac * 8) = v;
            }
            // B: 8B per pass, 16B-chunk XOR swizzle by (row&7)
            char* bbase = smem + 2 * A_BUF + boff_buf;
            #pragma unroll
            for (int s = 0; s < 4; s++) {
                int row = s * 8 + br;
                int ch  = bc >> 1;
                int chs = ch ^ (row & 7);
                uint2 v = make_uint2(pack_bf16(yb[s].x, yb[s].y),
                                     pack_bf16(yb[s].z, yb[s].w));
                *(uint2*)(bbase + row * 256 + chs * 16 + (bc & 1) * 8) = v;
            }
        }
        __syncthreads();

        // ---- prefetch next iter (overlaps with MMA below) ----
        if (it + 1 < ITERS) {
            const int kk = kk0 + (it + 1) * 32;
            #pragma unroll
            for (int s = 0; s < 8; s++)
                xa[s] = *(const float4*)(X + (size_t)(s * 32 + ar) * VOCAB + kk + ac * 4);
            #pragma unroll
            for (int s = 0; s < 4; s++)
                yb[s] = *(const float4*)(Y + (size_t)(kk + s * 8 + br) * D_ + bc * 4);
        }

        // ---- MMA: 2 k16-steps ----
        #pragma unroll
        for (int ks = 0; ks < 2; ks++) {
            uint32_t af[4][4];
            #pragma unroll
            for (int i = 0; i < 4; i++)
                ldsm4(af[i], abuf + a_off + i * (16 * A_ROWB) + ks * 32);
            const uint32_t brow_b = bbuf + b_off + ks * 16 * 256;
            #pragma unroll
            for (int jj = 0; jj < 4; jj++) {
                uint32_t bf[4];
                ldsm4t(bf, brow_b + b_swz[jj]);
                #pragma unroll
                for (int i = 0; i < 4; i++) {
                    mma16(c[i][jj * 2],     af[i], bf);
                    mma16(c[i][jj * 2 + 1], af[i], bf + 2);
                }
            }
        }
        __syncthreads();
    }

    // ---- epilogue: disjoint partial writes ----
    const int g = lane >> 2, t = lane & 3;
    float* P = &g_part[sp][row0][0];
    #pragma unroll
    for (int i = 0; i < 4; i++) {
        #pragma unroll
        for (int j = 0; j < 8; j++) {
            int m = wm * 64 + i * 16;
            int col = wn * 64 + j * 8 + 2 * t;
            *(float2*)&P[(size_t)(m + g) * D_ + col]     = make_float2(c[i][j][0], c[i][j][1]);
            *(float2*)&P[(size_t)(m + g + 8) * D_ + col] = make_float2(c[i][j][2], c[i][j][3]);
        }
    }
}

// ---------------- kernel 2: reduce partials + per-b dot products ----------------
__global__ __launch_bounds__(256) void finalize_a() {
    const int wid = threadIdx.x >> 5, lane = threadIdx.x & 31;
    const int b = blockIdx.x * 8 + wid;
    const int d = lane * 4;

    float4 e = make_float4(0.f, 0.f, 0.f, 0.f);
    float4 p = make_float4(0.f, 0.f, 0.f, 0.f);
    float4 nk[KNEG];
    #pragma unroll
    for (int k = 0; k < KNEG; k++) nk[k] = make_float4(0.f, 0.f, 0.f, 0.f);

    #pragma unroll
    for (int sp = 0; sp < SPLITS; sp++) {
        float4 v;
        v = *(const float4*)&g_part[sp][b][d];
        e.x += v.x; e.y += v.y; e.z += v.z; e.w += v.w;
        v = *(const float4*)&g_part[sp][1024 + b][d];
        p.x += v.x; p.y += v.y; p.z += v.z; p.w += v.w;
        #pragma unroll
        for (int k = 0; k < KNEG; k++) {
            v = *(const float4*)&g_part[sp][2048 + b * KNEG + k][d];
            nk[k].x += v.x; nk[k].y += v.y; nk[k].z += v.z; nk[k].w += v.w;
        }
    }

    float s = e.x * p.x + e.y * p.y + e.z * p.z + e.w * p.w;
    float bm[KNEG];
    #pragma unroll
    for (int k = 0; k < KNEG; k++)
        bm[k] = e.x * nk[k].x + e.y * nk[k].y + e.z * nk[k].z + e.w * nk[k].w;

    #pragma unroll
    for (int off = 16; off; off >>= 1) {
        s += __shfl_xor_sync(0xffffffffu, s, off);
        #pragma unroll
        for (int k = 0; k < KNEG; k++)
            bm[k] += __shfl_xor_sync(0xffffffffu, bm[k], off);
    }
    if (lane == 0) {
        g_s[b] = s;
        #pragma unroll
        for (int k = 0; k < KNEG; k++) g_bm[b * KNEG + k] = bm[k];
    }
}

// ---------------- kernel 3: loss ----------------
__device__ __forceinline__ float logsig(float x) {
    return fminf(x, 0.f) - log1pf(expf(-fabsf(x)));
}

__global__ void finalize_kernel(float* __restrict__ out) {
    __shared__ float red[B_];
    int b = threadIdx.x;
    float left  = logsig(g_s[b]);
    float right = 0.f;
    #pragma unroll
    for (int k = 0; k < KNEG; k++)
        right += logsig(-g_bm[b * KNEG + k]);
    red[b] = -(left + right);
    __syncthreads();
    for (int off = B_ / 2; off > 0; off >>= 1) {
        if (b < off) red[b] += red[b + off];
        __syncthreads();
    }
    if (b == 0) out[0] = red[0] / (float)B_;
}

// ---------------- launch ----------------
extern "C" void kernel_launch(void* const* d_in, const int* in_sizes, int n_in,
                              void* d_out, int out_size) {
    const float* vi  = (const float*)d_in[0];   // [B, VOC]
    const float* vo  = (const float*)d_in[1];   // [B, VOC]
    const float* neg = (const float*)d_in[2];   // [B, K, VOC]
    const float* V   = (const float*)d_in[3];   // [VOC, D]
    const float* U   = (const float*)d_in[4];   // [VOC, D]
    float* out = (float*)d_out;

    gemm_all<<<dim3(RTILES, SPLITS), 256>>>(vi, vo, neg, V, U);
    finalize_a<<<B_ / 8, 256>>>();
    finalize_kernel<<<1, B_>>>(out);
}

// round 9
// speedup vs baseline: 1.8539x; 1.0462x over previous
#include <cuda_runtime.h>
#include <cuda_bf16.h>
#include <math.h>
#include <stdint.h>

#define B_     1024
#define VOCAB  32000
#define D_     128
#define KNEG   5
#define ROWS_T 7168          // 1024 vi + 1024 vo + 5120 neg
#define RTILES 56            // 128-row tiles
#define SPLITS 5
#define CHUNK  6400          // VOCAB / SPLITS
#define ITERS  200           // CHUNK / 32

// smem:  A: [m=128][k=32] bf16, row pitch 80B (64B data + 16B pad).
//        B: [k=32][d=128] bf16, row 256B, 16B-chunk XOR-swizzled by (k&7).
// Double buffered (additive toggle).  2 CTAs / SM.
#define A_ROWB  80
#define A_BUF   (128 * A_ROWB)    // 10240
#define B_BUF   (32 * 256)        // 8192
#define SMEMSZ  (2 * A_BUF + 2 * B_BUF)   // 36864

// ---------------- device scratch ----------------
__device__ float g_part[SPLITS][ROWS_T][D_];   // split-K partials (18.3 MB)
__device__ float g_s[B_];
__device__ float g_bm[B_ * KNEG];

// ---------------- helpers ----------------
__device__ __forceinline__ uint32_t smem_u32(const void* p) {
    uint32_t a;
    asm("{ .reg .u64 t; cvta.to.shared.u64 t, %1; cvt.u32.u64 %0, t; }" : "=r"(a) : "l"(p));
    return a;
}
__device__ __forceinline__ uint32_t pack_bf16(float lo, float hi) {
    uint32_t u;
    asm("cvt.rn.bf16x2.f32 %0, %1, %2;" : "=r"(u) : "f"(hi), "f"(lo));
    return u;
}
__device__ __forceinline__ void ldsm4(uint32_t r[4], uint32_t addr) {
    asm volatile("ldmatrix.sync.aligned.m8n8.x4.shared.b16 {%0,%1,%2,%3}, [%4];"
                 : "=r"(r[0]), "=r"(r[1]), "=r"(r[2]), "=r"(r[3]) : "r"(addr));
}
__device__ __forceinline__ void ldsm4t(uint32_t r[4], uint32_t addr) {
    asm volatile("ldmatrix.sync.aligned.m8n8.x4.trans.shared.b16 {%0,%1,%2,%3}, [%4];"
                 : "=r"(r[0]), "=r"(r[1]), "=r"(r[2]), "=r"(r[3]) : "r"(addr));
}
__device__ __forceinline__ void mma16(float c[4], const uint32_t a[4], const uint32_t b[2]) {
    asm volatile(
        "mma.sync.aligned.m16n8k16.row.col.f32.bf16.bf16.f32 "
        "{%0,%1,%2,%3}, {%4,%5,%6,%7}, {%8,%9}, {%0,%1,%2,%3};"
        : "+f"(c[0]), "+f"(c[1]), "+f"(c[2]), "+f"(c[3])
        : "r"(a[0]), "r"(a[1]), "r"(a[2]), "r"(a[3]), "r"(b[0]), "r"(b[1]));
}

// ---------------- kernel 1: C_part[sp] = X_tile @ Y_chunk ----------------
// CTA tile 128m x 128n, BK=32.  8 warps as 4(m) x 2(n), warp tile 32x64.
// 2 CTAs per SM to hide barrier + memory latency.
__global__ __launch_bounds__(256, 2) void gemm_all(const float* __restrict__ vi,
                                                   const float* __restrict__ vo,
                                                   const float* __restrict__ neg,
                                                   const float* __restrict__ V,
                                                   const float* __restrict__ U) {
    __shared__ __align__(16) char smem[SMEMSZ];

    const int mt = blockIdx.x;                // row-tile 0..55
    const int sp = blockIdx.y;                // split   0..4
    const int row0 = mt * 128;
    const float* X = (mt < 8)  ? vi  + (size_t)row0 * VOCAB
                   : (mt < 16) ? vo  + (size_t)(row0 - 1024) * VOCAB
                               : neg + (size_t)(row0 - 2048) * VOCAB;
    const float* Y = (mt < 8) ? V : U;
    const int kk0 = sp * CHUNK;

    const int tid = threadIdx.x, lane = tid & 31, wid = tid >> 5;
    const int wm = wid >> 1, wn = wid & 1;    // 4 x 2

    const uint32_t sb = smem_u32(smem);

    // ---- loader roles (coalesced: consecutive lanes -> consecutive float4) ----
    // A: pass s (0..3): row = s*32 + (tid>>3), float4 col = tid&7
    const int ar = tid >> 3;
    const int ac = tid & 7;
    // B: pass s (0..3): row = s*8 + (tid>>5), float4 col = lane
    const int br = tid >> 5;
    const int bc = lane;

    // ---- fragment addresses (validated R5/R7/R8 maps; warp m-span 32) ----
    const uint32_t a_off = (uint32_t)(wm * 32 + (lane & 15)) * A_ROWB + ((lane >> 4) << 4);
    const int kl = (lane & 7) + ((lane >> 3) & 1) * 8;
    uint32_t b_swz[4];
    #pragma unroll
    for (int jj = 0; jj < 4; jj++)
        b_swz[jj] = (uint32_t)(((wn * 8 + jj * 2 + (lane >> 4)) ^ (lane & 7)) << 4);
    const uint32_t b_off = (uint32_t)kl * 256;

    float c[2][8][4] = {};
    float4 xa[4], yb[4];

    // prefetch iter 0
    {
        #pragma unroll
        for (int s = 0; s < 4; s++)
            xa[s] = *(const float4*)(X + (size_t)(s * 32 + ar) * VOCAB + kk0 + ac * 4);
        #pragma unroll
        for (int s = 0; s < 4; s++)
            yb[s] = *(const float4*)(Y + (size_t)(kk0 + s * 8 + br) * D_ + bc * 4);
    }

    for (int it = 0; it < ITERS; it++) {
        const uint32_t aoff_buf = (it & 1) ? A_BUF : 0;
        const uint32_t boff_buf = (it & 1) ? B_BUF : 0;
        const uint32_t abuf = sb + aoff_buf;
        const uint32_t bbuf = sb + 2 * A_BUF + boff_buf;

        // ---- stage regs -> smem (bf16) ----
        {
            char* abase = smem + aoff_buf;
            #pragma unroll
            for (int s = 0; s < 4; s++) {
                uint2 v = make_uint2(pack_bf16(xa[s].x, xa[s].y),
                                     pack_bf16(xa[s].z, xa[s].w));
                *(uint2*)(abase + (s * 32 + ar) * A_ROWB + ac * 8) = v;
            }
            char* bbase = smem + 2 * A_BUF + boff_buf;
            #pragma unroll
            for (int s = 0; s < 4; s++) {
                int row = s * 8 + br;
                int ch  = bc >> 1;
                int chs = ch ^ (row & 7);
                uint2 v = make_uint2(pack_bf16(yb[s].x, yb[s].y),
                                     pack_bf16(yb[s].z, yb[s].w));
                *(uint2*)(bbase + row * 256 + chs * 16 + (bc & 1) * 8) = v;
            }
        }
        __syncthreads();

        // ---- prefetch next iter (overlaps with MMA below) ----
        if (it + 1 < ITERS) {
            const int kk = kk0 + (it + 1) * 32;
            #pragma unroll
            for (int s = 0; s < 4; s++)
                xa[s] = *(const float4*)(X + (size_t)(s * 32 + ar) * VOCAB + kk + ac * 4);
            #pragma unroll
            for (int s = 0; s < 4; s++)
                yb[s] = *(const float4*)(Y + (size_t)(kk + s * 8 + br) * D_ + bc * 4);
        }

        // ---- MMA: 2 k16-steps ----
        #pragma unroll
        for (int ks = 0; ks < 2; ks++) {
            uint32_t af[2][4];
            ldsm4(af[0], abuf + a_off + ks * 32);
            ldsm4(af[1], abuf + a_off + 16 * A_ROWB + ks * 32);
            const uint32_t brow_b = bbuf + b_off + ks * 16 * 256;
            #pragma unroll
            for (int jj = 0; jj < 4; jj++) {
                uint32_t bf[4];
                ldsm4t(bf, brow_b + b_swz[jj]);
                mma16(c[0][jj * 2],     af[0], bf);
                mma16(c[0][jj * 2 + 1], af[0], bf + 2);
                mma16(c[1][jj * 2],     af[1], bf);
                mma16(c[1][jj * 2 + 1], af[1], bf + 2);
            }
        }
        __syncthreads();
    }

    // ---- epilogue: disjoint partial writes ----
    const int g = lane >> 2, t = lane & 3;
    float* P = &g_part[sp][row0][0];
    #pragma unroll
    for (int i = 0; i < 2; i++) {
        #pragma unroll
        for (int j = 0; j < 8; j++) {
            int m = wm * 32 + i * 16;
            int col = wn * 64 + j * 8 + 2 * t;
            *(float2*)&P[(size_t)(m + g) * D_ + col]     = make_float2(c[i][j][0], c[i][j][1]);
            *(float2*)&P[(size_t)(m + g + 8) * D_ + col] = make_float2(c[i][j][2], c[i][j][3]);
        }
    }
}

// ---------------- kernel 2: reduce partials + per-b dot products ----------------
__global__ __launch_bounds__(256) void finalize_a() {
    const int wid = threadIdx.x >> 5, lane = threadIdx.x & 31;
    const int b = blockIdx.x * 8 + wid;
    const int d = lane * 4;

    float4 e = make_float4(0.f, 0.f, 0.f, 0.f);
    float4 p = make_float4(0.f, 0.f, 0.f, 0.f);
    float4 nk[KNEG];
    #pragma unroll
    for (int k = 0; k < KNEG; k++) nk[k] = make_float4(0.f, 0.f, 0.f, 0.f);

    #pragma unroll
    for (int sp = 0; sp < SPLITS; sp++) {
        float4 v;
        v = *(const float4*)&g_part[sp][b][d];
        e.x += v.x; e.y += v.y; e.z += v.z; e.w += v.w;
        v = *(const float4*)&g_part[sp][1024 + b][d];
        p.x += v.x; p.y += v.y; p.z += v.z; p.w += v.w;
        #pragma unroll
        for (int k = 0; k < KNEG; k++) {
            v = *(const float4*)&g_part[sp][2048 + b * KNEG + k][d];
            nk[k].x += v.x; nk[k].y += v.y; nk[k].z += v.z; nk[k].w += v.w;
        }
    }

    float s = e.x * p.x + e.y * p.y + e.z * p.z + e.w * p.w;
    float bm[KNEG];
    #pragma unroll
    for (int k = 0; k < KNEG; k++)
        bm[k] = e.x * nk[k].x + e.y * nk[k].y + e.z * nk[k].z + e.w * nk[k].w;

    #pragma unroll
    for (int off = 16; off; off >>= 1) {
        s += __shfl_xor_sync(0xffffffffu, s, off);
        #pragma unroll
        for (int k = 0; k < KNEG; k++)
            bm[k] += __shfl_xor_sync(0xffffffffu, bm[k], off);
    }
    if (lane == 0) {
        g_s[b] = s;
        #pragma unroll
        for (int k = 0; k < KNEG; k++) g_bm[b * KNEG + k] = bm[k];
    }
}

// ---------------- kernel 3: loss ----------------
__device__ __forceinline__ float logsig(float x) {
    return fminf(x, 0.f) - log1pf(expf(-fabsf(x)));
}

__global__ void finalize_kernel(float* __restrict__ out) {
    __shared__ float red[B_];
    int b = threadIdx.x;
    float left  = logsig(g_s[b]);
    float right = 0.f;
    #pragma unroll
    for (int k = 0; k < KNEG; k++)
        right += logsig(-g_bm[b * KNEG + k]);
    red[b] = -(left + right);
    __syncthreads();
    for (int off = B_ / 2; off > 0; off >>= 1) {
        if (b < off) red[b] += red[b + off];
        __syncthreads();
    }
    if (b == 0) out[0] = red[0] / (float)B_;
}

// ---------------- launch ----------------
extern "C" void kernel_launch(void* const* d_in, const int* in_sizes, int n_in,
                              void* d_out, int out_size) {
    const float* vi  = (const float*)d_in[0];   // [B, VOC]
    const float* vo  = (const float*)d_in[1];   // [B, VOC]
    const float* neg = (const float*)d_in[2];   // [B, K, VOC]
    const float* V   = (const float*)d_in[3];   // [VOC, D]
    const float* U   = (const float*)d_in[4];   // [VOC, D]
    float* out = (float*)d_out;

    gemm_all<<<dim3(RTILES, SPLITS), 256>>>(vi, vo, neg, V, U);
    finalize_a<<<B_ / 8, 256>>>();
    finalize_kernel<<<1, B_>>>(out);
}

// round 10
// speedup vs baseline: 2.0115x; 1.0850x over previous
#include <cuda_runtime.h>
#include <cuda_bf16.h>
#include <math.h>
#include <stdint.h>

#define B_     1024
#define VOCAB  32000
#define D_     128
#define KNEG   5
#define ROWS_T 7168          // 1024 vi + 1024 vo + 5120 neg
#define RTILES 56            // 128-row tiles
#define SPLITS 5
#define CHUNK  6400          // VOCAB / SPLITS
#define ITERS  200           // CHUNK / 32

// smem:  A: [m=128][k=32] bf16, row pitch 80B.  B: [k=32][d=128] bf16,
// row 256B, 16B-chunk XOR-swizzled by (k&7).  Double buffered, 2 CTAs/SM.
#define A_ROWB  80
#define A_BUF   (128 * A_ROWB)    // 10240
#define B_BUF   (32 * 256)        // 8192
#define SMEMSZ  (2 * A_BUF + 2 * B_BUF)   // 36864

// ---------------- device scratch ----------------
__device__ float g_part[SPLITS][ROWS_T][D_];   // split-K partials (18.3 MB)
__device__ float g_s[B_];
__device__ float g_bm[B_ * KNEG];

// ---------------- helpers ----------------
__device__ __forceinline__ uint32_t smem_u32(const void* p) {
    uint32_t a;
    asm("{ .reg .u64 t; cvta.to.shared.u64 t, %1; cvt.u32.u64 %0, t; }" : "=r"(a) : "l"(p));
    return a;
}
__device__ __forceinline__ uint32_t pack_bf16(float lo, float hi) {
    uint32_t u;
    asm("cvt.rn.bf16x2.f32 %0, %1, %2;" : "=r"(u) : "f"(hi), "f"(lo));
    return u;
}
__device__ __forceinline__ void ldsm4(uint32_t r[4], uint32_t addr) {
    asm volatile("ldmatrix.sync.aligned.m8n8.x4.shared.b16 {%0,%1,%2,%3}, [%4];"
                 : "=r"(r[0]), "=r"(r[1]), "=r"(r[2]), "=r"(r[3]) : "r"(addr));
}
__device__ __forceinline__ void ldsm4t(uint32_t r[4], uint32_t addr) {
    asm volatile("ldmatrix.sync.aligned.m8n8.x4.trans.shared.b16 {%0,%1,%2,%3}, [%4];"
                 : "=r"(r[0]), "=r"(r[1]), "=r"(r[2]), "=r"(r[3]) : "r"(addr));
}
__device__ __forceinline__ void mma16(float c[4], const uint32_t a[4], const uint32_t b[2]) {
    asm volatile(
        "mma.sync.aligned.m16n8k16.row.col.f32.bf16.bf16.f32 "
        "{%0,%1,%2,%3}, {%4,%5,%6,%7}, {%8,%9}, {%0,%1,%2,%3};"
        : "+f"(c[0]), "+f"(c[1]), "+f"(c[2]), "+f"(c[3])
        : "r"(a[0]), "r"(a[1]), "r"(a[2]), "r"(a[3]), "r"(b[0]), "r"(b[1]));
}

// ---------------- kernel 1: C_part[sp] = X_tile @ Y_chunk ----------------
// CTA tile 128m x 128n, BK=32.  8 warps as 4(m) x 2(n), warp tile 32x64.
// Single __syncthreads per iter: MMA(cur) || STS(nxt) || LDG(it+2).
__global__ __launch_bounds__(256, 2) void gemm_all(const float* __restrict__ vi,
                                                   const float* __restrict__ vo,
                                                   const float* __restrict__ neg,
                                                   const float* __restrict__ V,
                                                   const float* __restrict__ U) {
    __shared__ __align__(16) char smem[SMEMSZ];

    const int mt = blockIdx.x;                // row-tile 0..55
    const int sp = blockIdx.y;                // split   0..4
    const int row0 = mt * 128;
    const float* X = (mt < 8)  ? vi  + (size_t)row0 * VOCAB
                   : (mt < 16) ? vo  + (size_t)(row0 - 1024) * VOCAB
                               : neg + (size_t)(row0 - 2048) * VOCAB;
    const float* Y = (mt < 8) ? V : U;
    const int kk0 = sp * CHUNK;

    const int tid = threadIdx.x, lane = tid & 31, wid = tid >> 5;
    const int wm = wid >> 1, wn = wid & 1;    // 4 x 2

    const uint32_t sb = smem_u32(smem);

    // ---- loader roles (coalesced) ----
    const int ar = tid >> 3;                  // A: row within pass
    const int ac = tid & 7;                   // A: float4 col
    const int br = tid >> 5;                  // B: row within pass
    const int bc = lane;                      // B: float4 col

    // ---- fragment addresses (validated maps) ----
    const uint32_t a_off = (uint32_t)(wm * 32 + (lane & 15)) * A_ROWB + ((lane >> 4) << 4);
    const int kl = (lane & 7) + ((lane >> 3) & 1) * 8;
    uint32_t b_swz[4];
    #pragma unroll
    for (int jj = 0; jj < 4; jj++)
        b_swz[jj] = (uint32_t)(((wn * 8 + jj * 2 + (lane >> 4)) ^ (lane & 7)) << 4);
    const uint32_t b_off = (uint32_t)kl * 256;

    float c[2][8][4] = {};
    float4 xa[4], yb[4];

    // ---- staging helpers ----
    auto do_ldg = [&](int it) {
        const int kk = kk0 + it * 32;
        #pragma unroll
        for (int s = 0; s < 4; s++)
            xa[s] = *(const float4*)(X + (size_t)(s * 32 + ar) * VOCAB + kk + ac * 4);
        #pragma unroll
        for (int s = 0; s < 4; s++)
            yb[s] = *(const float4*)(Y + (size_t)(kk + s * 8 + br) * D_ + bc * 4);
    };
    auto do_sts = [&](uint32_t aoff_buf, uint32_t boff_buf) {
        char* abase = smem + aoff_buf;
        #pragma unroll
        for (int s = 0; s < 4; s++) {
            uint2 v = make_uint2(pack_bf16(xa[s].x, xa[s].y),
                                 pack_bf16(xa[s].z, xa[s].w));
            *(uint2*)(abase + (s * 32 + ar) * A_ROWB + ac * 8) = v;
        }
        char* bbase = smem + 2 * A_BUF + boff_buf;
        #pragma unroll
        for (int s = 0; s < 4; s++) {
            int row = s * 8 + br;
            int chs = (bc >> 1) ^ (row & 7);
            uint2 v = make_uint2(pack_bf16(yb[s].x, yb[s].y),
                                 pack_bf16(yb[s].z, yb[s].w));
            *(uint2*)(bbase + row * 256 + chs * 16 + (bc & 1) * 8) = v;
        }
    };

    // ---- prologue: fill buf0 with iter0, prefetch iter1 into regs ----
    do_ldg(0);
    do_sts(0, 0);
    do_ldg(1);
    __syncthreads();

    for (int it = 0; it < ITERS; it++) {
        const uint32_t cur = (uint32_t)(it & 1);
        const uint32_t abuf = sb + cur * A_BUF;
        const uint32_t bbuf = sb + 2 * A_BUF + cur * B_BUF;

        // ---- MMA on current buffer ----
        #pragma unroll
        for (int ks = 0; ks < 2; ks++) {
            uint32_t af[2][4];
            ldsm4(af[0], abuf + a_off + ks * 32);
            ldsm4(af[1], abuf + a_off + 16 * A_ROWB + ks * 32);
            const uint32_t brow_b = bbuf + b_off + ks * 16 * 256;
            #pragma unroll
            for (int jj = 0; jj < 4; jj++) {
                uint32_t bf[4];
                ldsm4t(bf, brow_b + b_swz[jj]);
                mma16(c[0][jj * 2],     af[0], bf);
                mma16(c[0][jj * 2 + 1], af[0], bf + 2);
                mma16(c[1][jj * 2],     af[1], bf);
                mma16(c[1][jj * 2 + 1], af[1], bf + 2);
            }
        }

        // ---- stage it+1 into other buffer (disjoint from MMA reads) ----
        if (it + 1 < ITERS)
            do_sts((cur ^ 1) * A_BUF, (cur ^ 1) * B_BUF);
        // ---- prefetch it+2 (regs freed by the STS above) ----
        if (it + 2 < ITERS)
            do_ldg(it + 2);

        __syncthreads();
    }

    // ---- epilogue: disjoint partial writes ----
    const int g = lane >> 2, t = lane & 3;
    float* P = &g_part[sp][row0][0];
    #pragma unroll
    for (int i = 0; i < 2; i++) {
        #pragma unroll
        for (int j = 0; j < 8; j++) {
            int m = wm * 32 + i * 16;
            int col = wn * 64 + j * 8 + 2 * t;
            *(float2*)&P[(size_t)(m + g) * D_ + col]     = make_float2(c[i][j][0], c[i][j][1]);
            *(float2*)&P[(size_t)(m + g + 8) * D_ + col] = make_float2(c[i][j][2], c[i][j][3]);
        }
    }
}

// ---------------- kernel 2: reduce partials + per-b dot products ----------------
__global__ __launch_bounds__(256) void finalize_a() {
    const int wid = threadIdx.x >> 5, lane = threadIdx.x & 31;
    const int b = blockIdx.x * 8 + wid;
    const int d = lane * 4;

    float4 e = make_float4(0.f, 0.f, 0.f, 0.f);
    float4 p = make_float4(0.f, 0.f, 0.f, 0.f);
    float4 nk[KNEG];
    #pragma unroll
    for (int k = 0; k < KNEG; k++) nk[k] = make_float4(0.f, 0.f, 0.f, 0.f);

    #pragma unroll
    for (int sp = 0; sp < SPLITS; sp++) {
        float4 v;
        v = *(const float4*)&g_part[sp][b][d];
        e.x += v.x; e.y += v.y; e.z += v.z; e.w += v.w;
        v = *(const float4*)&g_part[sp][1024 + b][d];
        p.x += v.x; p.y += v.y; p.z += v.z; p.w += v.w;
        #pragma unroll
        for (int k = 0; k < KNEG; k++) {
            v = *(const float4*)&g_part[sp][2048 + b * KNEG + k][d];
            nk[k].x += v.x; nk[k].y += v.y; nk[k].z += v.z; nk[k].w += v.w;
        }
    }

    float s = e.x * p.x + e.y * p.y + e.z * p.z + e.w * p.w;
    float bm[KNEG];
    #pragma unroll
    for (int k = 0; k < KNEG; k++)
        bm[k] = e.x * nk[k].x + e.y * nk[k].y + e.z * nk[k].z + e.w * nk[k].w;

    #pragma unroll
    for (int off = 16; off; off >>= 1) {
        s += __shfl_xor_sync(0xffffffffu, s, off);
        #pragma unroll
        for (int k = 0; k < KNEG; k++)
            bm[k] += __shfl_xor_sync(0xffffffffu, bm[k], off);
    }
    if (lane == 0) {
        g_s[b] = s;
        #pragma unroll
        for (int k = 0; k < KNEG; k++) g_bm[b * KNEG + k] = bm[k];
    }
}

// ---------------- kernel 3: loss ----------------
__device__ __forceinline__ float logsig(float x) {
    return fminf(x, 0.f) - log1pf(expf(-fabsf(x)));
}

__global__ void finalize_kernel(float* __restrict__ out) {
    __shared__ float red[B_];
    int b = threadIdx.x;
    float left  = logsig(g_s[b]);
    float right = 0.f;
    #pragma unroll
    for (int k = 0; k < KNEG; k++)
        right += logsig(-g_bm[b * KNEG + k]);
    red[b] = -(left + right);
    __syncthreads();
    for (int off = B_ / 2; off > 0; off >>= 1) {
        if (b < off) red[b] += red[b + off];
        __syncthreads();
    }
    if (b == 0) out[0] = red[0] / (float)B_;
}

// ---------------- launch ----------------
extern "C" void kernel_launch(void* const* d_in, const int* in_sizes, int n_in,
                              void* d_out, int out_size) {
    const float* vi  = (const float*)d_in[0];   // [B, VOC]
    const float* vo  = (const float*)d_in[1];   // [B, VOC]
    const float* neg = (const float*)d_in[2];   // [B, K, VOC]
    const float* V   = (const float*)d_in[3];   // [VOC, D]
    const float* U   = (const float*)d_in[4];   // [VOC, D]
    float* out = (float*)d_out;

    gemm_all<<<dim3(RTILES, SPLITS), 256>>>(vi, vo, neg, V, U);
    finalize_a<<<B_ / 8, 256>>>();
    finalize_kernel<<<1, B_>>>(out);
}

// round 11
// speedup vs baseline: 2.0341x; 1.0112x over previous
#include <cuda_runtime.h>
#include <cuda_bf16.h>
#include <math.h>
#include <stdint.h>

#define B_     1024
#define VOCAB  32000
#define D_     128
#define KNEG   5
#define ROWS_T 7168          // 1024 vi + 1024 vo + 5120 neg
#define RTILES 28            // 256-row tiles
#define SPLITS 5
#define CHUNK  6400          // VOCAB / SPLITS
#define ITERS  200           // CHUNK / 32

// smem:  A: [m=256][k=32] bf16, row pitch 80B.  B: [k=32][d=128] bf16,
// row 256B, 16B-chunk XOR-swizzled by (k&7).  Double buffered, 1 CTA/SM.
#define A_ROWB  80
#define A_BUF   (256 * A_ROWB)    // 20480
#define B_BUF   (32 * 256)        // 8192
#define SMEMSZ  (2 * A_BUF + 2 * B_BUF)   // 57344

// ---------------- device scratch ----------------
__device__ float g_part[SPLITS][ROWS_T][D_];   // split-K partials (18.3 MB)
__device__ float g_s[B_];
__device__ float g_bm[B_ * KNEG];

// ---------------- helpers ----------------
__device__ __forceinline__ uint32_t smem_u32(const void* p) {
    uint32_t a;
    asm("{ .reg .u64 t; cvta.to.shared.u64 t, %1; cvt.u32.u64 %0, t; }" : "=r"(a) : "l"(p));
    return a;
}
__device__ __forceinline__ uint32_t pack_bf16(float lo, float hi) {
    uint32_t u;
    asm("cvt.rn.bf16x2.f32 %0, %1, %2;" : "=r"(u) : "f"(hi), "f"(lo));
    return u;
}
__device__ __forceinline__ void ldsm4(uint32_t r[4], uint32_t addr) {
    asm volatile("ldmatrix.sync.aligned.m8n8.x4.shared.b16 {%0,%1,%2,%3}, [%4];"
                 : "=r"(r[0]), "=r"(r[1]), "=r"(r[2]), "=r"(r[3]) : "r"(addr));
}
__device__ __forceinline__ void ldsm4t(uint32_t r[4], uint32_t addr) {
    asm volatile("ldmatrix.sync.aligned.m8n8.x4.trans.shared.b16 {%0,%1,%2,%3}, [%4];"
                 : "=r"(r[0]), "=r"(r[1]), "=r"(r[2]), "=r"(r[3]) : "r"(addr));
}
__device__ __forceinline__ void mma16(float c[4], const uint32_t a[4], const uint32_t b[2]) {
    asm volatile(
        "mma.sync.aligned.m16n8k16.row.col.f32.bf16.bf16.f32 "
        "{%0,%1,%2,%3}, {%4,%5,%6,%7}, {%8,%9}, {%0,%1,%2,%3};"
        : "+f"(c[0]), "+f"(c[1]), "+f"(c[2]), "+f"(c[3])
        : "r"(a[0]), "r"(a[1]), "r"(a[2]), "r"(a[3]), "r"(b[0]), "r"(b[1]));
}

// ---------------- kernel 1: C_part[sp] = X_tile @ Y_chunk ----------------
// CTA tile 256m x 128n, BK=32.  8 warps as 4(m) x 2(n), warp tile 64x64.
// Single __syncthreads per iter: MMA(cur) || STS(it+1) || LDG(it+2).
__global__ __launch_bounds__(256, 1) void gemm_all(const float* __restrict__ vi,
                                                   const float* __restrict__ vo,
                                                   const float* __restrict__ neg,
                                                   const float* __restrict__ V,
                                                   const float* __restrict__ U) {
    __shared__ __align__(16) char smem[SMEMSZ];

    const int mt = blockIdx.x;                // row-tile 0..27
    const int sp = blockIdx.y;                // split   0..4
    const int row0 = mt * 256;
    const float* X = (mt < 4) ? vi  + (size_t)row0 * VOCAB
                   : (mt < 8) ? vo  + (size_t)(row0 - 1024) * VOCAB
                              : neg + (size_t)(row0 - 2048) * VOCAB;
    const float* Y = (mt < 4) ? V : U;
    const int kk0 = sp * CHUNK;

    const int tid = threadIdx.x, lane = tid & 31, wid = tid >> 5;
    const int wm = wid >> 1, wn = wid & 1;    // 4 x 2

    const uint32_t sb = smem_u32(smem);

    // ---- loader roles (coalesced; validated in R8) ----
    const int ar = tid >> 3;                  // A: row within pass (s*32 + ar)
    const int ac = tid & 7;                   // A: float4 col
    const int br = tid >> 5;                  // B: row within pass (s*8 + br)
    const int bc = lane;                      // B: float4 col

    // ---- fragment addresses (validated R8 maps; warp m-span 64) ----
    const uint32_t a_off = (uint32_t)(wm * 64 + (lane & 15)) * A_ROWB + ((lane >> 4) << 4);
    const int kl = (lane & 7) + ((lane >> 3) & 1) * 8;
    uint32_t b_swz[4];
    #pragma unroll
    for (int jj = 0; jj < 4; jj++)
        b_swz[jj] = (uint32_t)(((wn * 8 + jj * 2 + (lane >> 4)) ^ (lane & 7)) << 4);
    const uint32_t b_off = (uint32_t)kl * 256;

    float c[4][8][4] = {};
    float4 xa[8], yb[4];

    // ---- staging helpers ----
    auto do_ldg = [&](int it) {
        const int kk = kk0 + it * 32;
        #pragma unroll
        for (int s = 0; s < 8; s++)
            xa[s] = *(const float4*)(X + (size_t)(s * 32 + ar) * VOCAB + kk + ac * 4);
        #pragma unroll
        for (int s = 0; s < 4; s++)
            yb[s] = *(const float4*)(Y + (size_t)(kk + s * 8 + br) * D_ + bc * 4);
    };
    auto do_sts = [&](uint32_t aoff_buf, uint32_t boff_buf) {
        char* abase = smem + aoff_buf;
        #pragma unroll
        for (int s = 0; s < 8; s++) {
            uint2 v = make_uint2(pack_bf16(xa[s].x, xa[s].y),
                                 pack_bf16(xa[s].z, xa[s].w));
            *(uint2*)(abase + (s * 32 + ar) * A_ROWB + ac * 8) = v;
        }
        char* bbase = smem + 2 * A_BUF + boff_buf;
        #pragma unroll
        for (int s = 0; s < 4; s++) {
            int row = s * 8 + br;
            int chs = (bc >> 1) ^ (row & 7);
            uint2 v = make_uint2(pack_bf16(yb[s].x, yb[s].y),
                                 pack_bf16(yb[s].z, yb[s].w));
            *(uint2*)(bbase + row * 256 + chs * 16 + (bc & 1) * 8) = v;
        }
    };

    // ---- prologue: fill buf0 with iter0, prefetch iter1 into regs ----
    do_ldg(0);
    do_sts(0, 0);
    do_ldg(1);
    __syncthreads();

    for (int it = 0; it < ITERS; it++) {
        const uint32_t cur = (uint32_t)(it & 1);
        const uint32_t abuf = sb + cur * A_BUF;
        const uint32_t bbuf = sb + 2 * A_BUF + cur * B_BUF;

        // ---- MMA on current buffer ----
        #pragma unroll
        for (int ks = 0; ks < 2; ks++) {
            uint32_t af[4][4];
            #pragma unroll
            for (int i = 0; i < 4; i++)
                ldsm4(af[i], abuf + a_off + i * (16 * A_ROWB) + ks * 32);
            const uint32_t brow_b = bbuf + b_off + ks * 16 * 256;
            #pragma unroll
            for (int jj = 0; jj < 4; jj++) {
                uint32_t bf[4];
                ldsm4t(bf, brow_b + b_swz[jj]);
                #pragma unroll
                for (int i = 0; i < 4; i++) {
                    mma16(c[i][jj * 2],     af[i], bf);
                    mma16(c[i][jj * 2 + 1], af[i], bf + 2);
                }
            }
        }

        // ---- stage it+1 into other buffer (disjoint from MMA reads) ----
        if (it + 1 < ITERS)
            do_sts((cur ^ 1) * A_BUF, (cur ^ 1) * B_BUF);
        // ---- prefetch it+2 (regs freed by the STS above) ----
        if (it + 2 < ITERS)
            do_ldg(it + 2);

        __syncthreads();
    }

    // ---- epilogue: disjoint partial writes ----
    const int g = lane >> 2, t = lane & 3;
    float* P = &g_part[sp][row0][0];
    #pragma unroll
    for (int i = 0; i < 4; i++) {
        #pragma unroll
        for (int j = 0; j < 8; j++) {
            int m = wm * 64 + i * 16;
            int col = wn * 64 + j * 8 + 2 * t;
            *(float2*)&P[(size_t)(m + g) * D_ + col]     = make_float2(c[i][j][0], c[i][j][1]);
            *(float2*)&P[(size_t)(m + g + 8) * D_ + col] = make_float2(c[i][j][2], c[i][j][3]);
        }
    }
}

// ---------------- kernel 2: reduce partials + per-b dot products ----------------
__global__ __launch_bounds__(256) void finalize_a() {
    const int wid = threadIdx.x >> 5, lane = threadIdx.x & 31;
    const int b = blockIdx.x * 8 + wid;
    const int d = lane * 4;

    float4 e = make_float4(0.f, 0.f, 0.f, 0.f);
    float4 p = make_float4(0.f, 0.f, 0.f, 0.f);
    float4 nk[KNEG];
    #pragma unroll
    for (int k = 0; k < KNEG; k++) nk[k] = make_float4(0.f, 0.f, 0.f, 0.f);

    #pragma unroll
    for (int sp = 0; sp < SPLITS; sp++) {
        float4 v;
        v = *(const float4*)&g_part[sp][b][d];
        e.x += v.x; e.y += v.y; e.z += v.z; e.w += v.w;
        v = *(const float4*)&g_part[sp][1024 + b][d];
        p.x += v.x; p.y += v.y; p.z += v.z; p.w += v.w;
        #pragma unroll
        for (int k = 0; k < KNEG; k++) {
            v = *(const float4*)&g_part[sp][2048 + b * KNEG + k][d];
            nk[k].x += v.x; nk[k].y += v.y; nk[k].z += v.z; nk[k].w += v.w;
        }
    }

    float s = e.x * p.x + e.y * p.y + e.z * p.z + e.w * p.w;
    float bm[KNEG];
    #pragma unroll
    for (int k = 0; k < KNEG; k++)
        bm[k] = e.x * nk[k].x + e.y * nk[k].y + e.z * nk[k].z + e.w * nk[k].w;

    #pragma unroll
    for (int off = 16; off; off >>= 1) {
        s += __shfl_xor_sync(0xffffffffu, s, off);
        #pragma unroll
        for (int k = 0; k < KNEG; k++)
            bm[k] += __shfl_xor_sync(0xffffffffu, bm[k], off);
    }
    if (lane == 0) {
        g_s[b] = s;
        #pragma unroll
        for (int k = 0; k < KNEG; k++) g_bm[b * KNEG + k] = bm[k];
    }
}

// ---------------- kernel 3: loss ----------------
__device__ __forceinline__ float logsig(float x) {
    return fminf(x, 0.f) - log1pf(expf(-fabsf(x)));
}

__global__ void finalize_kernel(float* __restrict__ out) {
    __shared__ float red[B_];
    int b = threadIdx.x;
    float left  = logsig(g_s[b]);
    float right = 0.f;
    #pragma unroll
    for (int k = 0; k < KNEG; k++)
        right += logsig(-g_bm[b * KNEG + k]);
    red[b] = -(left + right);
    __syncthreads();
    for (int off = B_ / 2; off > 0; off >>= 1) {
        if (b < off) red[b] += red[b + off];
        __syncthreads();
    }
    if (b == 0) out[0] = red[0] / (float)B_;
}

// ---------------- launch ----------------
extern "C" void kernel_launch(void* const* d_in, const int* in_sizes, int n_in,
                              void* d_out, int out_size) {
    const float* vi  = (const float*)d_in[0];   // [B, VOC]
    const float* vo  = (const float*)d_in[1];   // [B, VOC]
    const float* neg = (const float*)d_in[2];   // [B, K, VOC]
    const float* V   = (const float*)d_in[3];   // [VOC, D]
    const float* U   = (const float*)d_in[4];   // [VOC, D]
    float* out = (float*)d_out;

    gemm_all<<<dim3(RTILES, SPLITS), 256>>>(vi, vo, neg, V, U);
    finalize_a<<<B_ / 8, 256>>>();
    finalize_kernel<<<1, B_>>>(out);
}